// round 17
// baseline (speedup 1.0000x reference)
#include <cuda_runtime.h>
#include <cuda_bf16.h>
#include <cstdint>

// S=4096, H=3, E=512, G=3334, F=1, res=0.03
// out = sum_{s,h,e} mask*(b_h + w_h*feat)  -  0.03 * sum_{s,h,g} exp(b_h + w_h*grid)
//
// R6 structure (best known: pair/half partition, contiguous float2 walk)
// + prefetch.global.L2 8 iterations (2KB) ahead in the grid loop to raise
// memory-level parallelism without spending registers or SMEM.

#define S_DIM 4096
#define H_DIM 3
#define E_DIM 512
#define G_DIM 3334

constexpr int NBLK = 1024;
constexpr int NTHR = 256;
constexpr int NW   = NTHR / 32;

constexpr int EV_ROW4 = E_DIM / 4;            // 128 float4 per event row
constexpr int GR_ROW2 = G_DIM / 2;            // 1667 float2 per grid row
constexpr int GR_HALF_ITERS = 26;             // 26*32 = 832 float2 per half
constexpr int GR_SPLIT = 832;                 // half1 covers [832, 1667)
constexpr int PF_DIST = 8;                    // prefetch distance (iterations)

__device__ float g_part_log[NBLK];
__device__ float g_part_int[NBLK];
__device__ unsigned int g_done_count = 0;

__device__ __forceinline__ void prefetch_l2(const void* p) {
    asm volatile("prefetch.global.L2 [%0];" :: "l"(p));
}

__global__ void __launch_bounds__(NTHR, 8) lm_fused_kernel(
    const float* __restrict__ ev_feat,
    const int* __restrict__ ev_mask,      // bool -> int32 in the harness
    const float* __restrict__ gr_feat,
    const float* __restrict__ weights,
    const float* __restrict__ bases,
    const float* __restrict__ effects,
    float* __restrict__ out)
{
    const int lane = threadIdx.x & 31;
    const int wi   = threadIdx.x >> 5;
    const int warp = blockIdx.x * NW + wi;             // 0..8191
    const int pair = warp >> 1;                        // 0..4095
    const int half = warp & 1;                         // 0 or 1

    constexpr float LOG2E = 1.4426950408889634f;
    const float wv0 = weights[0] * effects[0];
    const float wv1 = weights[1] * effects[1];
    const float wv2 = weights[2] * effects[2];
    const float bv0 = bases[0], bv1 = bases[1], bv2 = bases[2];
    const float wl0 = wv0 * LOG2E, wl1 = wv1 * LOG2E, wl2 = wv2 * LOG2E;
    const float bl0 = bv0 * LOG2E, bl1 = bv1 * LOG2E, bl2 = bv2 * LOG2E;

    float plog = 0.0f;
    float pint0 = 0.0f;
    float pint1 = 0.0f;

    // ---- Event part: rows 3*pair + h, this warp's half (64 float4 each) ----
    {
        const int kbase = half * (EV_ROW4 / 2) + lane;   // 0/64 + lane
        #pragma unroll
        for (int h = 0; h < 3; h++) {
            const int row = 3 * pair + h;
            const float4* __restrict__ f4 = (const float4*)ev_feat + (size_t)row * EV_ROW4;
            const int4*   __restrict__ m4 = (const int4*)ev_mask + (size_t)row * EV_ROW4;
            int   cnt = 0;
            float sum = 0.0f;
            #pragma unroll
            for (int i = 0; i < 2; i++) {
                const int k = kbase + 32 * i;
                const float4 f = f4[k];
                const int4   m = m4[k];
                if (m.x) { cnt++; sum += f.x; }
                if (m.y) { cnt++; sum += f.y; }
                if (m.z) { cnt++; sum += f.z; }
                if (m.w) { cnt++; sum += f.w; }
            }
            const float wh = (h == 0) ? wv0 : ((h == 1) ? wv1 : wv2);
            const float bh = (h == 0) ? bv0 : ((h == 1) ? bv1 : bv2);
            plog += fmaf(bh, (float)cnt, wh * sum);
        }
    }

    // ---- Grid part: rows 3*pair + h, contiguous float2 walk + L2 prefetch ----
    {
        const int kbase = half * GR_SPLIT + lane;
        #pragma unroll
        for (int h = 0; h < 3; h++) {
            const int row = 3 * pair + h;
            const float2* __restrict__ g2 = (const float2*)gr_feat + (size_t)row * GR_ROW2;
            const float ww = (h == 0) ? wl0 : ((h == 1) ? wl1 : wl2);
            const float bb = (h == 0) ? bl0 : ((h == 1) ? bl1 : bl2);
            float acc = 0.0f;
            #pragma unroll 4
            for (int i = 0; i < GR_HALF_ITERS; i++) {
                const int k = kbase + 32 * i;
                prefetch_l2((const void*)(g2 + k + 32 * PF_DIST));   // hint, non-faulting
                const float2 g = g2[k];
                acc   += exp2f(fmaf(ww, g.x, bb));
                pint1 += exp2f(fmaf(ww, g.y, bb));
            }
            if (half == 1 && lane < GR_ROW2 - 2 * GR_SPLIT) {   // tail: 1664..1666 (3 float2)
                const float2 g = g2[2 * GR_SPLIT + lane];
                acc   += exp2f(fmaf(ww, g.x, bb));
                pint1 += exp2f(fmaf(ww, g.y, bb));
            }
            pint0 += acc;
        }
    }

    float pint = pint0 + pint1;

    // ---- Block reduction ----
    __shared__ float s_log[NW];
    __shared__ float s_int[NW];
    __shared__ bool s_is_last;
    #pragma unroll
    for (int off = 16; off > 0; off >>= 1) {
        plog += __shfl_xor_sync(0xFFFFFFFFu, plog, off);
        pint += __shfl_xor_sync(0xFFFFFFFFu, pint, off);
    }
    if (lane == 0) { s_log[wi] = plog; s_int[wi] = pint; }
    __syncthreads();
    if (wi == 0) {
        float vl = (lane < NW) ? s_log[lane] : 0.0f;
        float vi = (lane < NW) ? s_int[lane] : 0.0f;
        #pragma unroll
        for (int off = 4; off > 0; off >>= 1) {
            vl += __shfl_xor_sync(0xFFFFFFFFu, vl, off);
            vi += __shfl_xor_sync(0xFFFFFFFFu, vi, off);
        }
        if (lane == 0) {
            g_part_log[blockIdx.x] = vl;
            g_part_int[blockIdx.x] = vi;
            __threadfence();
            unsigned int ticket = atomicAdd(&g_done_count, 1u);
            s_is_last = (ticket == (unsigned int)(NBLK - 1));
        }
    }
    __syncthreads();

    // ---- Last block: deterministic final combine in double ----
    if (s_is_last) {
        __shared__ double d_log[NW];
        __shared__ double d_int[NW];
        double dl = 0.0, di = 0.0;
        for (int j = threadIdx.x; j < NBLK; j += NTHR) {
            dl += (double)g_part_log[j];
            di += (double)g_part_int[j];
        }
        #pragma unroll
        for (int off = 16; off > 0; off >>= 1) {
            dl += __shfl_xor_sync(0xFFFFFFFFu, dl, off);
            di += __shfl_xor_sync(0xFFFFFFFFu, di, off);
        }
        if (lane == 0) { d_log[wi] = dl; d_int[wi] = di; }
        __syncthreads();
        if (threadIdx.x == 0) {
            double tl = 0.0, ti = 0.0;
            #pragma unroll
            for (int k = 0; k < NW; k++) { tl += d_log[k]; ti += d_int[k]; }
            out[0] = (float)(tl - 0.03 * ti);
            g_done_count = 0;   // reset for next graph replay
        }
    }
}

extern "C" void kernel_launch(void* const* d_in, const int* in_sizes, int n_in,
                              void* d_out, int out_size)
{
    const float* ev_feat = (const float*)d_in[0];
    const int*   ev_mask = (const int*)d_in[1];
    const float* gr_feat = (const float*)d_in[2];
    const float* weights = (const float*)d_in[3];
    const float* bases   = (const float*)d_in[4];
    const float* effects = (const float*)d_in[5];
    float* out = (float*)d_out;

    lm_fused_kernel<<<NBLK, NTHR>>>(ev_feat, ev_mask, gr_feat, weights, bases, effects, out);
}